// round 2
// baseline (speedup 1.0000x reference)
#include <cuda_runtime.h>

#define N_NODES 100000
#define E_EDGES 800000
#define H_HEADS 12
#define F_FEATS 8
#define D_DIM 96          // H*F
#define NH (N_NODES * H_HEADS)
#define LRELU_SLOPE 0.2f

// ---------------- scratch (static device globals; no allocation) -------------
// float4-typed so 16B alignment is guaranteed (raw float[] casts trap).
__device__ float4 g_s_src4[N_NODES * 3];     // [N,H] source scores (12 floats = 3 float4)
__device__ float4 g_s_trg4[N_NODES * 3];     // [N,H] target scores
__device__ float4 g_denom4[N_NODES * 3];     // [N,H] softmax denominators
__device__ float4 g_agg[N_NODES * (D_DIM/4)];// [N, 24] float4 = [N,96] accum
__device__ int    g_idx[2 * E_EDGES];        // normalized int32 edge index
__device__ int    g_is64;                    // dtype flag

// ---------------- pass 0a: detect edge_index dtype ---------------------------
__global__ void detect_kernel(const int* __restrict__ ei32) {
    if (blockIdx.x == 0 && threadIdx.x == 0) {
        int allz = 1;
        #pragma unroll
        for (int i = 1; i < 128; i += 2) allz &= (ei32[i] == 0);
        g_is64 = allz;   // all high words zero -> int64 layout
    }
}

// ---------------- pass 0b: normalize edge_index to int32 ---------------------
__global__ void convert_kernel(const void* __restrict__ ei) {
    int i = blockIdx.x * blockDim.x + threadIdx.x;
    if (i >= 2 * E_EDGES) return;
    int v;
    if (g_is64) v = (int)((const long long*)ei)[i];
    else        v = ((const int*)ei)[i];
    g_idx[i] = v;
}

// ---------------- pass 1: per-(node,head) scores + zero scratch --------------
__global__ void node_scores_kernel(const float* __restrict__ x,
                                   const float* __restrict__ score_src,
                                   const float* __restrict__ score_trg) {
    int idx = blockIdx.x * blockDim.x + threadIdx.x;   // idx = n*12 + h
    if (idx >= NH) return;
    int h = idx % H_HEADS;

    // x[n*96 + h*8 .. +7] == x[idx*8 .. +7]
    const float4* xp = reinterpret_cast<const float4*>(x) + idx * 2;
    float4 xa = xp[0];
    float4 xb = xp[1];

    const float4* sa = reinterpret_cast<const float4*>(score_src) + h * 2;
    const float4* ta = reinterpret_cast<const float4*>(score_trg) + h * 2;
    float4 s0 = sa[0], s1 = sa[1];
    float4 t0 = ta[0], t1 = ta[1];

    float ssrc = xa.x*s0.x + xa.y*s0.y + xa.z*s0.z + xa.w*s0.w
               + xb.x*s1.x + xb.y*s1.y + xb.z*s1.z + xb.w*s1.w;
    float strg = xa.x*t0.x + xa.y*t0.y + xa.z*t0.z + xa.w*t0.w
               + xb.x*t1.x + xb.y*t1.y + xb.z*t1.z + xb.w*t1.w;

    reinterpret_cast<float*>(g_s_src4)[idx] = ssrc;
    reinterpret_cast<float*>(g_s_trg4)[idx] = strg;
    reinterpret_cast<float*>(g_denom4)[idx] = 0.0f;
    // zero agg: NH threads cover 2 float4 each (NH*2 == N*24)
    float4 z = make_float4(0.f, 0.f, 0.f, 0.f);
    g_agg[idx * 2]     = z;
    g_agg[idx * 2 + 1] = z;
}

// ---------------- pass 2: edge softmax denominators --------------------------
// one thread per (edge, head-quad); 3 threads per edge; float4 atomic into denom
__global__ void edge_denom_kernel() {
    int gid = blockIdx.x * blockDim.x + threadIdx.x;
    if (gid >= E_EDGES * 3) return;
    int e = gid / 3;
    int j = gid - e * 3;                 // head quad 0..2
    int src = g_idx[e];
    int trg = g_idx[E_EDGES + e];

    float4 a = g_s_src4[src * 3 + j];
    float4 b = g_s_trg4[trg * 3 + j];

    float4 v;
    float s;
    s = a.x + b.x; s = (s >= 0.f) ? s : LRELU_SLOPE * s; v.x = __expf(s);
    s = a.y + b.y; s = (s >= 0.f) ? s : LRELU_SLOPE * s; v.y = __expf(s);
    s = a.z + b.z; s = (s >= 0.f) ? s : LRELU_SLOPE * s; v.z = __expf(s);
    s = a.w + b.w; s = (s >= 0.f) ? s : LRELU_SLOPE * s; v.w = __expf(s);

    atomicAdd(&g_denom4[trg * 3 + j], v);
}

// ---------------- pass 3: weighted aggregation -------------------------------
// one thread per (edge, 16B chunk of the feature row); 24 threads per edge.
// consecutive threads read consecutive float4s of x[src] -> coalesced row gather.
__global__ void edge_agg_kernel(const float4* __restrict__ x4) {
    int gid = blockIdx.x * blockDim.x + threadIdx.x;
    if (gid >= E_EDGES * 24) return;
    int e = gid / 24;
    int c = gid - e * 24;                // chunk 0..23, head h = c>>1
    int h = c >> 1;
    int src = g_idx[e];
    int trg = g_idx[E_EDGES + e];

    float s = reinterpret_cast<const float*>(g_s_src4)[src * H_HEADS + h]
            + reinterpret_cast<const float*>(g_s_trg4)[trg * H_HEADS + h];
    s = (s >= 0.f) ? s : LRELU_SLOPE * s;
    float ex = __expf(s);
    float attn = ex / (reinterpret_cast<const float*>(g_denom4)[trg * H_HEADS + h] + 1e-16f);

    float4 xv = x4[src * 24 + c];
    float4 w = make_float4(xv.x * attn, xv.y * attn, xv.z * attn, xv.w * attn);
    atomicAdd(&g_agg[trg * 24 + c], w);
}

// ---------------- pass 4: RMS norm + GEMM (out = x + normed @ W^T) -----------
// 16 nodes per block, 128 threads. W in smem (row-padded to 25 float4 for
// conflict-free lane access). Warp w handles nodes 4w..4w+3; lane computes
// output dims d = lane, lane+32, lane+64.
__global__ __launch_bounds__(128) void norm_gemm_kernel(
        const float* __restrict__ x,
        const float* __restrict__ wproj,
        const float* __restrict__ lnw,
        float* __restrict__ out) {
    __shared__ float4 Wp[96][25];    // W[d][k-chunk], 24 used + pad
    __shared__ float4 sm_n[16][25];  // normalized node features
    __shared__ float  sm_rms[16];

    int tid = threadIdx.x;
    int node0 = blockIdx.x * 16;

    // load W (2304 float4)
    const float4* w4 = reinterpret_cast<const float4*>(wproj);
    for (int i = tid; i < 96 * 24; i += 128) {
        int r = i / 24, c2 = i - r * 24;
        Wp[r][c2] = w4[i];
    }
    // load agg rows for 16 nodes (384 float4)
    for (int i = tid; i < 16 * 24; i += 128) {
        int nd = i / 24, c2 = i - nd * 24;
        sm_n[nd][c2] = g_agg[(node0 + nd) * 24 + c2];
    }
    __syncthreads();

    // sum of squares: 8 threads per node, 3 float4 each, shfl-reduce
    {
        int nd = tid >> 3, part = tid & 7;
        float ssum = 0.f;
        #pragma unroll
        for (int j = 0; j < 3; j++) {
            float4 v = sm_n[nd][part * 3 + j];
            ssum += v.x * v.x + v.y * v.y + v.z * v.z + v.w * v.w;
        }
        ssum += __shfl_down_sync(0xffffffffu, ssum, 4);
        ssum += __shfl_down_sync(0xffffffffu, ssum, 2);
        ssum += __shfl_down_sync(0xffffffffu, ssum, 1);
        if (part == 0)
            sm_rms[nd] = rsqrtf(ssum * (1.0f / 96.0f) + 1e-6f);
    }
    __syncthreads();

    // scale by rms * ln_weight
    for (int i = tid; i < 16 * 24; i += 128) {
        int nd = i / 24, c2 = i - nd * 24;
        float r = sm_rms[nd];
        float4 v = sm_n[nd][c2];
        float4 lw = reinterpret_cast<const float4*>(lnw)[c2];
        v.x *= r * lw.x; v.y *= r * lw.y; v.z *= r * lw.z; v.w *= r * lw.w;
        sm_n[nd][c2] = v;
    }
    __syncthreads();

    // GEMM: 4 warps x 4 nodes, lane -> dims {lane, lane+32, lane+64}
    int wp = tid >> 5, lane = tid & 31;
    float acc[4][3];
    #pragma unroll
    for (int a = 0; a < 4; a++)
        #pragma unroll
        for (int b = 0; b < 3; b++) acc[a][b] = 0.f;

    #pragma unroll 4
    for (int k = 0; k < 24; k++) {
        float4 w0 = Wp[lane][k];
        float4 w1 = Wp[lane + 32][k];
        float4 w2 = Wp[lane + 64][k];
        #pragma unroll
        for (int a = 0; a < 4; a++) {
            float4 nb = sm_n[wp * 4 + a][k];
            acc[a][0] += nb.x * w0.x + nb.y * w0.y + nb.z * w0.z + nb.w * w0.w;
            acc[a][1] += nb.x * w1.x + nb.y * w1.y + nb.z * w1.z + nb.w * w1.w;
            acc[a][2] += nb.x * w2.x + nb.y * w2.y + nb.z * w2.z + nb.w * w2.w;
        }
    }

    #pragma unroll
    for (int a = 0; a < 4; a++) {
        int n = node0 + wp * 4 + a;
        out[n * 96 + lane]      = x[n * 96 + lane]      + acc[a][0];
        out[n * 96 + lane + 32] = x[n * 96 + lane + 32] + acc[a][1];
        out[n * 96 + lane + 64] = x[n * 96 + lane + 64] + acc[a][2];
    }
}

// ---------------- launch ------------------------------------------------------
extern "C" void kernel_launch(void* const* d_in, const int* in_sizes, int n_in,
                              void* d_out, int out_size) {
    const float* x   = (const float*)d_in[0];
    const void*  ei  = d_in[1];
    const float* w   = (const float*)d_in[2];
    const float* ss  = (const float*)d_in[3];
    const float* st  = (const float*)d_in[4];
    const float* lnw = (const float*)d_in[5];
    float*       out = (float*)d_out;

    detect_kernel<<<1, 32>>>((const int*)ei);
    convert_kernel<<<(2 * E_EDGES + 255) / 256, 256>>>(ei);
    node_scores_kernel<<<(NH + 255) / 256, 256>>>(x, ss, st);
    edge_denom_kernel<<<(E_EDGES * 3 + 255) / 256, 256>>>();
    edge_agg_kernel<<<(E_EDGES * 24 + 255) / 256, 256>>>(
        reinterpret_cast<const float4*>(x));
    norm_gemm_kernel<<<N_NODES / 16, 128>>>(x, w, lnw, out);
}